// round 9
// baseline (speedup 1.0000x reference)
#include <cuda_runtime.h>
#include <math.h>

#define Hh   16
#define DU   64
#define DP   32
#define Dd   96
#define Bn   16
#define TCACHE 4095
#define TT   4096
#define WIN  512
#define Fdim 1536

#define TILE_R 32                 // rows per tile
#define NTILES 16                 // WIN / TILE_R
#define NBUF   4                  // ring depth
#define ROWF   104                // padded row stride in floats (conflict-free octet reads)
#define TILE_F (TILE_R * ROWF)    // 3328 floats = 13312 B per tile
#define ROWB   (Dd * 4)           // 384 bytes payload per row

static __device__ __forceinline__ unsigned smem_u32(const void* p) {
    return (unsigned)__cvta_generic_to_shared(p);
}
static __device__ __forceinline__ void mbar_init(unsigned a, unsigned cnt) {
    asm volatile("mbarrier.init.shared.b64 [%0], %1;" :: "r"(a), "r"(cnt) : "memory");
}
static __device__ __forceinline__ void mbar_expect(unsigned a, unsigned bytes) {
    asm volatile("mbarrier.arrive.expect_tx.shared.b64 _, [%0], %1;" :: "r"(a), "r"(bytes) : "memory");
}
static __device__ __forceinline__ void bulk_g2s(unsigned dst, const void* src, unsigned bytes, unsigned mbar) {
    asm volatile("cp.async.bulk.shared::cluster.global.mbarrier::complete_tx::bytes [%0], [%1], %2, [%3];"
                 :: "r"(dst), "l"(src), "r"(bytes), "r"(mbar) : "memory");
}
static __device__ __forceinline__ void mbar_wait(unsigned a, unsigned parity) {
    asm volatile(
        "{\n\t"
        ".reg .pred P;\n\t"
        "WAIT_%=: mbarrier.try_wait.parity.acquire.cta.shared::cta.b64 P, [%0], %1;\n\t"
        "@P bra DONE_%=;\n\t"
        "bra WAIT_%=;\n\t"
        "DONE_%=:\n\t"
        "}" :: "r"(a), "r"(parity) : "memory");
}
static __device__ __forceinline__ void fence_proxy_async_cta() {
    asm volatile("fence.proxy.async.shared::cta;" ::: "memory");
}

__global__ __launch_bounds__(256, 2)
void bichan_attn_kernel(const float* __restrict__ content,
                        const float* __restrict__ cache,
                        const float* __restrict__ Wq_u, const float* __restrict__ bq_u,
                        const float* __restrict__ Wk_u, const float* __restrict__ bk_u,
                        const float* __restrict__ Wv_u, const float* __restrict__ bv_u,
                        const float* __restrict__ Wq_p, const float* __restrict__ bq_p,
                        const float* __restrict__ Wk_p, const float* __restrict__ bk_p,
                        const float* __restrict__ Wv_p, const float* __restrict__ bv_p,
                        const float* __restrict__ pos_param_p,
                        float* __restrict__ out)
{
    extern __shared__ __align__(16) float s_tiles[];   // NBUF * TILE_F floats

    const int h    = blockIdx.x;
    const int b    = blockIdx.y;
    const int tid  = threadIdx.x;
    const int lane = tid & 31;
    const int w    = tid >> 5;
    const int qq   = lane >> 3;   // quarter: row within the warp's 4-row group
    const int s    = lane & 7;    // sublane: 12 dims of the row
    const int s4   = s * 4;
    const int r    = (w << 2) | qq;   // row 0..31 within a tile

    __shared__ float s_u[Dd];
    __shared__ float s_q[Dd];
    __shared__ alignas(16) float s_qt[Dd];
    __shared__ float s_bias[WIN];
    __shared__ float s_const;
    __shared__ float s_gm[32], s_gl[32];
    __shared__ alignas(16) float s_gacc[32][Dd];
    __shared__ alignas(16) float s_cbar[Dd];
    __shared__ alignas(8) unsigned long long s_mbar[NBUF];

    const float  pp    = *pos_param_p;
    const float* crow  = content + (size_t)b * Fdim + h * Dd;
    const float* cbase = cache   + ((size_t)b * TCACHE) * Fdim + h * Dd;

    const unsigned tile_base = smem_u32(s_tiles);
    const unsigned mbar_base = smem_u32(s_mbar);

    // ---- bulk-async tile producer: warp 0, one 384B row per lane ----
    auto issue_tile = [&](int t) {
        const int slot = t & (NBUF - 1);
        const unsigned mb = mbar_base + slot * 8;
        if (lane == 0) mbar_expect(mb, TILE_R * ROWB);
        __syncwarp();
        int j = (TT - WIN) + t * TILE_R + lane;
        const float* src = (j < TCACHE) ? (cbase + (size_t)j * Fdim) : crow;
        bulk_g2s(tile_base + (unsigned)(slot * TILE_F + lane * ROWF) * 4u, src, ROWB, mb);
    };

    // Init ring + kick off 3 tiles immediately (overlaps with projections below).
    if (w == 0) {
        if (lane == 0) {
            #pragma unroll
            for (int i = 0; i < NBUF; i++) mbar_init(mbar_base + i * 8, 1);
            fence_proxy_async_cta();
        }
        __syncwarp();
        issue_tile(0);
        issue_tile(1);
        issue_tile(2);
    }

    if (tid < Dd) s_u[tid] = crow[tid];

    // time_mask collapses to a uniform shift (softmax-invariant) -> ignored.
    for (int p = tid; p < WIN; p += 256) {
        int n = (WIN - 1) - p;
        float bucket;
        if (n < 16) bucket = (float)n;
        else {
            int bb = 16 + (int)((log((double)n * (1.0 / 16.0)) / log(8.0)) * 16.0);
            bucket = (float)(bb < 31 ? bb : 31);
        }
        s_bias[p] = -pp * bucket;
    }
    __syncthreads();

    // ---- q projection ----
    if (tid < DU) {
        const float* Wc = Wq_u + ((size_t)h * DU) * DU + tid;
        float acc = bq_u[h * DU + tid];
        #pragma unroll 8
        for (int d = 0; d < DU; d++) acc = fmaf(s_u[d], Wc[d * DU], acc);
        s_q[tid] = acc;
    } else if (tid < Dd) {
        int e = tid - DU;
        const float* Wc = Wq_p + ((size_t)h * DP) * DP + e;
        float acc = bq_p[h * DP + e];
        #pragma unroll 8
        for (int d = 0; d < DP; d++) acc = fmaf(s_u[DU + d], Wc[d * DP], acc);
        s_q[tid] = acc;
    }
    __syncthreads();

    // ---- fold K projection: qt = (Wk q)/sqrt(D), const = (q.bk)/sqrt(D) ----
    const float inv = 1.0f / sqrtf((float)Dd);
    if (tid < DU) {
        const float4* Wr = (const float4*)(Wk_u + ((size_t)h * DU + tid) * DU);
        float acc = 0.f;
        #pragma unroll
        for (int e4 = 0; e4 < DU / 4; e4++) {
            float4 wv = Wr[e4];
            acc += wv.x * s_q[e4*4] + wv.y * s_q[e4*4+1] + wv.z * s_q[e4*4+2] + wv.w * s_q[e4*4+3];
        }
        s_qt[tid] = acc * inv;
    } else if (tid < Dd) {
        int d = tid - DU;
        const float4* Wr = (const float4*)(Wk_p + ((size_t)h * DP + d) * DP);
        float acc = 0.f;
        #pragma unroll
        for (int e4 = 0; e4 < DP / 4; e4++) {
            float4 wv = Wr[e4];
            acc += wv.x * s_q[DU+e4*4] + wv.y * s_q[DU+e4*4+1] + wv.z * s_q[DU+e4*4+2] + wv.w * s_q[DU+e4*4+3];
        }
        s_qt[tid] = acc * inv;
    } else if (tid == Dd) {
        float acc = 0.f;
        for (int e = 0; e < DU; e++) acc = fmaf(s_q[e],      bk_u[h * DU + e], acc);
        for (int e = 0; e < DP; e++) acc = fmaf(s_q[DU + e], bk_p[h * DP + e], acc);
        s_const = acc * inv;
    }
    __syncthreads();

    // ---- main pass: bulk-async pipelined online softmax ----
    const float4* q4 = (const float4*)s_qt;
    const float4  qtA = q4[s], qtB = q4[8 + s], qtC = q4[16 + s];
    const float   sc  = s_const;

    float m = -INFINITY, l = 0.f;
    float4 aA = {0,0,0,0}, aB = {0,0,0,0}, aC = {0,0,0,0};

    for (int t = 0; t < NTILES; t++) {
        mbar_wait(mbar_base + (t & (NBUF - 1)) * 8, (t >> 2) & 1);
        __syncthreads();                       // all warps past tile t-1's buffer
        if (w == 0 && t + NBUF - 1 < NTILES) issue_tile(t + NBUF - 1);

        const float* B = s_tiles + (size_t)(t & (NBUF - 1)) * TILE_F + r * ROWF;
        float4 va = *(const float4*)(B + s4);
        float4 vb = *(const float4*)(B + 32 + s4);
        float4 vc = *(const float4*)(B + 64 + s4);

        float x;
        x = va.x * qtA.x;          x = fmaf(va.y, qtA.y, x);
        x = fmaf(va.z, qtA.z, x);  x = fmaf(va.w, qtA.w, x);
        x = fmaf(vb.x, qtB.x, x);  x = fmaf(vb.y, qtB.y, x);
        x = fmaf(vb.z, qtB.z, x);  x = fmaf(vb.w, qtB.w, x);
        x = fmaf(vc.x, qtC.x, x);  x = fmaf(vc.y, qtC.y, x);
        x = fmaf(vc.z, qtC.z, x);  x = fmaf(vc.w, qtC.w, x);
        x += __shfl_xor_sync(0xffffffffu, x, 1);
        x += __shfl_xor_sync(0xffffffffu, x, 2);
        x += __shfl_xor_sync(0xffffffffu, x, 4);

        float score = x + sc + s_bias[t * TILE_R + r];
        float mnew  = fmaxf(m, score);
        float corr  = __expf(m - mnew);
        float e     = __expf(score - mnew);
        l = fmaf(l, corr, e);
        aA.x = fmaf(aA.x, corr, e * va.x); aA.y = fmaf(aA.y, corr, e * va.y);
        aA.z = fmaf(aA.z, corr, e * va.z); aA.w = fmaf(aA.w, corr, e * va.w);
        aB.x = fmaf(aB.x, corr, e * vb.x); aB.y = fmaf(aB.y, corr, e * vb.y);
        aB.z = fmaf(aB.z, corr, e * vb.z); aB.w = fmaf(aB.w, corr, e * vb.w);
        aC.x = fmaf(aC.x, corr, e * vc.x); aC.y = fmaf(aC.y, corr, e * vc.y);
        aC.z = fmaf(aC.z, corr, e * vc.z); aC.w = fmaf(aC.w, corr, e * vc.w);
        m = mnew;
    }

    // ---- write 32 partial softmax groups (warp x quarter) ----
    if (s == 0) { s_gm[r] = m; s_gl[r] = l; }
    *(float4*)&s_gacc[r][s4]      = aA;
    *(float4*)&s_gacc[r][32 + s4] = aB;
    *(float4*)&s_gacc[r][64 + s4] = aC;
    __syncthreads();

    // ---- combine 32 groups ----
    if (tid < Dd) {
        float M = s_gm[0];
        #pragma unroll
        for (int gg = 1; gg < 32; gg++) M = fmaxf(M, s_gm[gg]);
        float L = 0.f, a = 0.f;
        #pragma unroll
        for (int gg = 0; gg < 32; gg++) {
            float scl = __expf(s_gm[gg] - M);
            L = fmaf(s_gl[gg], scl, L);
            a = fmaf(s_gacc[gg][tid], scl, a);
        }
        s_cbar[tid] = a / L;
    }
    __syncthreads();

    // ---- output projection through Wv + residual ----
    if (tid < DU) {
        const float* Wc = Wv_u + ((size_t)h * DU) * DU + tid;
        float acc = bv_u[h * DU + tid];
        #pragma unroll 8
        for (int d = 0; d < DU; d++) acc = fmaf(s_cbar[d], Wc[d * DU], acc);
        out[(size_t)b * Fdim + h * Dd + tid] = acc + s_u[tid];
    } else if (tid < Dd) {
        int e = tid - DU;
        const float* Wc = Wv_p + ((size_t)h * DP) * DP + e;
        float acc = bv_p[h * DP + e];
        #pragma unroll 8
        for (int d = 0; d < DP; d++) acc = fmaf(s_cbar[DU + d], Wc[d * DP], acc);
        out[(size_t)b * Fdim + h * Dd + tid] = acc + s_u[tid];
    }
}

extern "C" void kernel_launch(void* const* d_in, const int* in_sizes, int n_in,
                              void* d_out, int out_size)
{
    const float* content = (const float*)d_in[1];
    const float* cache   = (const float*)d_in[3];
    const float* Wq_u    = (const float*)d_in[5];
    const float* bq_u    = (const float*)d_in[6];
    const float* Wk_u    = (const float*)d_in[7];
    const float* bk_u    = (const float*)d_in[8];
    const float* Wv_u    = (const float*)d_in[9];
    const float* bv_u    = (const float*)d_in[10];
    const float* Wq_p    = (const float*)d_in[11];
    const float* bq_p    = (const float*)d_in[12];
    const float* Wk_p    = (const float*)d_in[13];
    const float* bk_p    = (const float*)d_in[14];
    const float* Wv_p    = (const float*)d_in[15];
    const float* bv_p    = (const float*)d_in[16];
    const float* pos_p   = (const float*)d_in[17];
    float* out = (float*)d_out;

    const int dyn_smem = NBUF * TILE_F * (int)sizeof(float);   // 53248 B
    cudaFuncSetAttribute(bichan_attn_kernel,
                         cudaFuncAttributeMaxDynamicSharedMemorySize, dyn_smem);

    dim3 grid(Hh, Bn);
    bichan_attn_kernel<<<grid, 256, dyn_smem>>>(content, cache,
                                                Wq_u, bq_u, Wk_u, bk_u, Wv_u, bv_u,
                                                Wq_p, bq_p, Wk_p, bk_p, Wv_p, bv_p,
                                                pos_p, out);
}

// round 10
// speedup vs baseline: 2.7220x; 2.7220x over previous
#include <cuda_runtime.h>
#include <math.h>

#define Hh   16
#define DU   64
#define DP   32
#define Dd   96
#define Bn   16
#define TCACHE 4095
#define TT   4096
#define WIN  512
#define Fdim 1536

__global__ __launch_bounds__(256, 2)
void bichan_attn_kernel(const float* __restrict__ content,
                        const float* __restrict__ cache,
                        const float* __restrict__ Wq_u, const float* __restrict__ bq_u,
                        const float* __restrict__ Wk_u, const float* __restrict__ bk_u,
                        const float* __restrict__ Wv_u, const float* __restrict__ bv_u,
                        const float* __restrict__ Wq_p, const float* __restrict__ bq_p,
                        const float* __restrict__ Wk_p, const float* __restrict__ bk_p,
                        const float* __restrict__ Wv_p, const float* __restrict__ bv_p,
                        const float* __restrict__ pos_param_p,
                        float* __restrict__ out)
{
    const int h    = blockIdx.x;
    const int b    = blockIdx.y;
    const int tid  = threadIdx.x;
    const int lane = tid & 31;
    const int w    = tid >> 5;
    const int qq   = lane >> 3;   // quarter: which of 4 positions per iteration
    const int s    = lane & 7;    // sublane: 12 dims of the row
    const int s4   = s * 4;

    __shared__ float s_u[Dd];
    __shared__ float s_q[Dd];
    __shared__ alignas(16) float s_qt[Dd];
    __shared__ float s_bias[WIN];
    __shared__ float s_const;
    __shared__ float s_gm[32], s_gl[32];
    __shared__ alignas(16) float s_gacc[32][Dd];
    __shared__ alignas(16) float s_cbar[Dd];

    const float  pp   = *pos_param_p;
    const float* crow = content + (size_t)b * Fdim + h * Dd;

    if (tid < Dd) s_u[tid] = crow[tid];

    // time_mask collapses to a uniform shift (softmax-invariant) -> ignored.
    // T5 bucket in fp32 via MUFU lg2: nearest floor boundary is 0.028 away,
    // __logf abs error ~2.5e-6 in the product -> exact bucket match with the
    // float64 reference. n >= 113 always buckets to 31 (16 + floor(16*ln(n/16)/ln 8)
    // reaches 31 at n=113 and caps at 31 through n=511).
    for (int p = tid; p < WIN; p += 256) {
        int n = (WIN - 1) - p;
        float bucket;
        if (n < 16)       bucket = (float)n;
        else if (n >= 113) bucket = 31.0f;
        else {
            // 16/ln(8) = 7.6936565...
            int bb = 16 + (int)(__logf((float)n * 0.0625f) * 7.69365658f);
            bucket = (float)bb;
        }
        s_bias[p] = -pp * bucket;
    }
    __syncthreads();

    // ---- q projection ----
    if (tid < DU) {
        const float* Wc = Wq_u + ((size_t)h * DU) * DU + tid;
        float acc = bq_u[h * DU + tid];
        #pragma unroll 8
        for (int d = 0; d < DU; d++) acc = fmaf(s_u[d], Wc[d * DU], acc);
        s_q[tid] = acc;
    } else if (tid < Dd) {
        int e = tid - DU;
        const float* Wc = Wq_p + ((size_t)h * DP) * DP + e;
        float acc = bq_p[h * DP + e];
        #pragma unroll 8
        for (int d = 0; d < DP; d++) acc = fmaf(s_u[DU + d], Wc[d * DP], acc);
        s_q[tid] = acc;
    }
    __syncthreads();

    // ---- fold K projection: qt = (Wk q)/sqrt(D), const = (q.bk)/sqrt(D) ----
    const float inv = 1.0f / sqrtf((float)Dd);
    if (tid < DU) {
        const float4* Wr = (const float4*)(Wk_u + ((size_t)h * DU + tid) * DU);
        float acc = 0.f;
        #pragma unroll
        for (int e4 = 0; e4 < DU / 4; e4++) {
            float4 wv = Wr[e4];
            acc += wv.x * s_q[e4*4] + wv.y * s_q[e4*4+1] + wv.z * s_q[e4*4+2] + wv.w * s_q[e4*4+3];
        }
        s_qt[tid] = acc * inv;
    } else if (tid < Dd) {
        int d = tid - DU;
        const float4* Wr = (const float4*)(Wk_p + ((size_t)h * DP + d) * DP);
        float acc = 0.f;
        #pragma unroll
        for (int e4 = 0; e4 < DP / 4; e4++) {
            float4 wv = Wr[e4];
            acc += wv.x * s_q[DU+e4*4] + wv.y * s_q[DU+e4*4+1] + wv.z * s_q[DU+e4*4+2] + wv.w * s_q[DU+e4*4+3];
        }
        s_qt[tid] = acc * inv;
    } else if (tid == Dd) {
        float acc = 0.f;
        for (int e = 0; e < DU; e++) acc = fmaf(s_q[e],      bk_u[h * DU + e], acc);
        for (int e = 0; e < DP; e++) acc = fmaf(s_q[DU + e], bk_p[h * DP + e], acc);
        s_const = acc * inv;
    }
    __syncthreads();

    // ---- main pass: octet-parallel online softmax, 1-deep register prefetch ----
    // Warp w, iteration i: positions p = w*64 + i*4 + qq (one per quarter).
    // Lane owns 12 dims: s*4+{0..3}, 32+s*4+{0..3}, 64+s*4+{0..3}.
    const float4* q4 = (const float4*)s_qt;
    const float4  qtA = q4[s], qtB = q4[8 + s], qtC = q4[16 + s];
    const float   sc  = s_const;
    const float*  cbase = cache + ((size_t)b * TCACHE) * Fdim + h * Dd;

    float m = -INFINITY, l = 0.f;
    float4 aA = {0,0,0,0}, aB = {0,0,0,0}, aC = {0,0,0,0};

    const float* r0;
    {
        int j = (TT - WIN) + w * 64 + qq;
        r0 = (j < TCACHE) ? (cbase + (size_t)j * Fdim) : crow;
    }
    float4 nva = *(const float4*)(r0 + s4);
    float4 nvb = *(const float4*)(r0 + 32 + s4);
    float4 nvc = *(const float4*)(r0 + 64 + s4);

    #pragma unroll 2
    for (int i = 0; i < 16; i++) {
        float4 va = nva, vb = nvb, vc = nvc;
        if (i < 15) {
            int j = (TT - WIN) + w * 64 + (i + 1) * 4 + qq;
            const float* r = (j < TCACHE) ? (cbase + (size_t)j * Fdim) : crow;
            nva = *(const float4*)(r + s4);
            nvb = *(const float4*)(r + 32 + s4);
            nvc = *(const float4*)(r + 64 + s4);
        }
        float x;
        x = va.x * qtA.x;          x = fmaf(va.y, qtA.y, x);
        x = fmaf(va.z, qtA.z, x);  x = fmaf(va.w, qtA.w, x);
        x = fmaf(vb.x, qtB.x, x);  x = fmaf(vb.y, qtB.y, x);
        x = fmaf(vb.z, qtB.z, x);  x = fmaf(vb.w, qtB.w, x);
        x = fmaf(vc.x, qtC.x, x);  x = fmaf(vc.y, qtC.y, x);
        x = fmaf(vc.z, qtC.z, x);  x = fmaf(vc.w, qtC.w, x);
        x += __shfl_xor_sync(0xffffffffu, x, 1);
        x += __shfl_xor_sync(0xffffffffu, x, 2);
        x += __shfl_xor_sync(0xffffffffu, x, 4);

        float score = x + sc + s_bias[w * 64 + i * 4 + qq];
        float mnew  = fmaxf(m, score);
        float corr  = __expf(m - mnew);
        float e     = __expf(score - mnew);
        l = fmaf(l, corr, e);
        aA.x = fmaf(aA.x, corr, e * va.x); aA.y = fmaf(aA.y, corr, e * va.y);
        aA.z = fmaf(aA.z, corr, e * va.z); aA.w = fmaf(aA.w, corr, e * va.w);
        aB.x = fmaf(aB.x, corr, e * vb.x); aB.y = fmaf(aB.y, corr, e * vb.y);
        aB.z = fmaf(aB.z, corr, e * vb.z); aB.w = fmaf(aB.w, corr, e * vb.w);
        aC.x = fmaf(aC.x, corr, e * vc.x); aC.y = fmaf(aC.y, corr, e * vc.y);
        aC.z = fmaf(aC.z, corr, e * vc.z); aC.w = fmaf(aC.w, corr, e * vc.w);
        m = mnew;
    }

    // ---- write 32 partial softmax groups (warp x quarter) ----
    const int g = (w << 2) | qq;
    if (s == 0) { s_gm[g] = m; s_gl[g] = l; }
    *(float4*)&s_gacc[g][s4]      = aA;
    *(float4*)&s_gacc[g][32 + s4] = aB;
    *(float4*)&s_gacc[g][64 + s4] = aC;
    __syncthreads();

    // ---- combine 32 groups ----
    if (tid < Dd) {
        float M = s_gm[0];
        #pragma unroll
        for (int gg = 1; gg < 32; gg++) M = fmaxf(M, s_gm[gg]);
        float L = 0.f, a = 0.f;
        #pragma unroll
        for (int gg = 0; gg < 32; gg++) {
            float scl = __expf(s_gm[gg] - M);
            L = fmaf(s_gl[gg], scl, L);
            a = fmaf(s_gacc[gg][tid], scl, a);
        }
        s_cbar[tid] = a / L;
    }
    __syncthreads();

    // ---- output projection through Wv + residual ----
    if (tid < DU) {
        const float* Wc = Wv_u + ((size_t)h * DU) * DU + tid;
        float acc = bv_u[h * DU + tid];
        #pragma unroll 8
        for (int d = 0; d < DU; d++) acc = fmaf(s_cbar[d], Wc[d * DU], acc);
        out[(size_t)b * Fdim + h * Dd + tid] = acc + s_u[tid];
    } else if (tid < Dd) {
        int e = tid - DU;
        const float* Wc = Wv_p + ((size_t)h * DP) * DP + e;
        float acc = bv_p[h * DP + e];
        #pragma unroll 8
        for (int d = 0; d < DP; d++) acc = fmaf(s_cbar[DU + d], Wc[d * DP], acc);
        out[(size_t)b * Fdim + h * Dd + tid] = acc + s_u[tid];
    }
}

extern "C" void kernel_launch(void* const* d_in, const int* in_sizes, int n_in,
                              void* d_out, int out_size)
{
    const float* content = (const float*)d_in[1];
    const float* cache   = (const float*)d_in[3];
    const float* Wq_u    = (const float*)d_in[5];
    const float* bq_u    = (const float*)d_in[6];
    const float* Wk_u    = (const float*)d_in[7];
    const float* bk_u    = (const float*)d_in[8];
    const float* Wv_u    = (const float*)d_in[9];
    const float* bv_u    = (const float*)d_in[10];
    const float* Wq_p    = (const float*)d_in[11];
    const float* bq_p    = (const float*)d_in[12];
    const float* Wk_p    = (const float*)d_in[13];
    const float* bk_p    = (const float*)d_in[14];
    const float* Wv_p    = (const float*)d_in[15];
    const float* bv_p    = (const float*)d_in[16];
    const float* pos_p   = (const float*)d_in[17];
    float* out = (float*)d_out;

    dim3 grid(Hh, Bn);
    bichan_attn_kernel<<<grid, 256>>>(content, cache,
                                      Wq_u, bq_u, Wk_u, bk_u, Wv_u, bv_u,
                                      Wq_p, bq_p, Wk_p, bk_p, Wv_p, bv_p,
                                      pos_p, out);
}